// round 15
// baseline (speedup 1.0000x reference)
#include <cuda_runtime.h>
#include <cuda_bf16.h>
#include <cuda_fp16.h>
#include <cstdint>

// Problem constants
#define S_LEN 2048
#define BATCH 2
#define DM    1024
#define NH    16
#define DKH   64
#define MROWS (BATCH * S_LEN)   // 4096

// ---------------------------------------------------------------------------
// Scratch (__device__ globals)
// ---------------------------------------------------------------------------
__device__ __half g_x16[(size_t)MROWS * DM];
__device__ __half g_wq16[(size_t)DM * DM];
__device__ __half g_wk16[(size_t)DM * DM];
__device__ __half g_wv16[(size_t)DM * DM];
__device__ __half g_wo16[(size_t)DM * DM];

__device__ __half g_Q16[(size_t)MROWS * DM];
__device__ __half g_K16[(size_t)MROWS * DM];
__device__ __half g_V16[(size_t)MROWS * DM];
__device__ __half g_Oa16[(size_t)MROWS * DM];

// ---------------------------------------------------------------------------
// Fused fp32 -> fp16 round of x + 4 weights, MLP=4 per thread
// ---------------------------------------------------------------------------
#define NX4 (MROWS * DM / 4)     // 1048576
#define NW4 (DM * DM / 4)        // 262144 = 1<<18
#define NTOT (NX4 + 4 * NW4)     // 2097152
#define RSTRIDE (NTOT / 4)       // 524288

__global__ __launch_bounds__(256) void round_all(
    const float* __restrict__ x,
    const float* __restrict__ wq, const float* __restrict__ wk,
    const float* __restrict__ wv, const float* __restrict__ wo,
    __half* __restrict__ x16,
    __half* __restrict__ wq16, __half* __restrict__ wk16,
    __half* __restrict__ wv16, __half* __restrict__ wo16)
{
    const int base = blockIdx.x * 256 + threadIdx.x;
    float4 v[4];
    __half2* dsts[4];
#pragma unroll
    for (int u = 0; u < 4; u++) {
        int i = base + u * RSTRIDE;
        const float* src;
        __half* dst;
        int off;
        if (i < NX4) {
            src = x; dst = x16; off = i;
        } else {
            int j = i - NX4;
            int w = j >> 18;
            off = j & (NW4 - 1);
            src = (w == 0) ? wq : (w == 1) ? wk : (w == 2) ? wv : wo;
            dst = (w == 0) ? wq16 : (w == 1) ? wk16 : (w == 2) ? wv16 : wo16;
        }
        v[u] = ((const float4*)src)[off];
        dsts[u] = ((__half2*)dst) + 2 * off;
    }
#pragma unroll
    for (int u = 0; u < 4; u++) {
        dsts[u][0] = __float22half2_rn(make_float2(v[u].x, v[u].y));
        dsts[u][1] = __float22half2_rn(make_float2(v[u].z, v[u].w));
    }
}

// ---------------------------------------------------------------------------
// Common helpers
// ---------------------------------------------------------------------------
__device__ __forceinline__ void ldsm_x4(unsigned* r, const void* p) {
    unsigned addr = (unsigned)__cvta_generic_to_shared(p);
    asm volatile("ldmatrix.sync.aligned.m8n8.x4.shared.b16 {%0,%1,%2,%3},[%4];"
                 : "=r"(r[0]), "=r"(r[1]), "=r"(r[2]), "=r"(r[3]) : "r"(addr));
}
__device__ __forceinline__ void ldsm_x4_t(unsigned* r, const void* p) {
    unsigned addr = (unsigned)__cvta_generic_to_shared(p);
    asm volatile("ldmatrix.sync.aligned.m8n8.x4.trans.shared.b16 {%0,%1,%2,%3},[%4];"
                 : "=r"(r[0]), "=r"(r[1]), "=r"(r[2]), "=r"(r[3]) : "r"(addr));
}
__device__ __forceinline__ void mma_f16(float* d, const unsigned* a, const unsigned* b) {
    asm volatile(
        "mma.sync.aligned.m16n8k16.row.col.f32.f16.f16.f32 "
        "{%0,%1,%2,%3},{%4,%5,%6,%7},{%8,%9},{%0,%1,%2,%3};"
        : "+f"(d[0]), "+f"(d[1]), "+f"(d[2]), "+f"(d[3])
        : "r"(a[0]), "r"(a[1]), "r"(a[2]), "r"(a[3]), "r"(b[0]), "r"(b[1]));
}
__device__ __forceinline__ void cp16(void* smem, const void* g) {
    unsigned s = (unsigned)__cvta_generic_to_shared(smem);
    asm volatile("cp.async.cg.shared.global [%0], [%1], 16;" :: "r"(s), "l"(g));
}
__device__ __forceinline__ void cp16s(unsigned s, const void* g) {
    asm volatile("cp.async.cg.shared.global [%0], [%1], 16;" :: "r"(s), "l"(g));
}
__device__ __forceinline__ void cp_commit() { asm volatile("cp.async.commit_group;"); }
__device__ __forceinline__ void cp_wait0()  { asm volatile("cp.async.wait_group 0;"); }
__device__ __forceinline__ unsigned pack_hf2(float2 f) {
    __half2 h = __float22half2_rn(f);
    return *(unsigned*)&h;
}

// ---------------------------------------------------------------------------
// Shared GEMM config: block 128x128, 256 thr (8 warps, 2x4), warp tile 64x32,
// K-chunk 32, 3-stage cp.async pipeline, 2 CTAs/SM.
// ---------------------------------------------------------------------------
#define G_ARR   10240                  // bytes per smem array (128 x 40 halves)
#define G_BUF   (2 * G_ARR)            // A, B = 20480
#define G_SMEM  (3 * G_BUF)            // 61440 (3 stages)

extern __shared__ char sm_raw[];

// fp32-accumulator GEMM body (OUT: 0 = fp32 out, 1 = fp16 out)
template<int OUT>
__device__ __forceinline__ void gemm_body(
    const __half* __restrict__ A, const __half* __restrict__ B,
    float* __restrict__ C, __half* __restrict__ Ch,
    float scale, int row0, int col0)
{
    const int tid  = threadIdx.x;
    const int lane = tid & 31;
    const int wid  = tid >> 5;
    const int wm   = wid & 1;
    const int wn   = wid >> 1;
    const int N = DM, K = DM;

    const unsigned smem_u = (unsigned)__cvta_generic_to_shared(sm_raw);

    float acc[4][4][4];
#pragma unroll
    for (int i = 0; i < 4; i++)
#pragma unroll
        for (int j = 0; j < 4; j++)
#pragma unroll
            for (int e = 0; e < 4; e++) acc[i][j][e] = 0.f;

    const int a_r = lane & 15;
    const int a_c = (lane >> 4) << 3;
    const int b_r = ((lane >> 4) << 3) + (lane & 7);
    const int b_c = ((lane >> 3) & 1) << 3;

    auto stage = [&](int c, int bb) {
        const int kk = c * 32;
        const unsigned base = smem_u + bb * G_BUF;
#pragma unroll
        for (int u = 0; u < 2; u++) {
            int g = tid + u * 256;
            int r = g >> 2;
            int q = (g & 3) * 8;
            size_t ga = (size_t)(row0 + r) * K + kk + q;
            size_t gb = (size_t)(col0 + r) * K + kk + q;
            unsigned so = (unsigned)(r * 40 + q) * 2;
            cp16s(base + so,         A + ga);
            cp16s(base + G_ARR + so, B + gb);
        }
        cp_commit();
    };

    const int nchunk = K / 32;           // 32
    stage(0, 0);
    stage(1, 1);

    int buf = 0;
    for (int c = 0; c < nchunk; c++) {
        if (c + 1 < nchunk) {
            asm volatile("cp.async.wait_group 1;" ::: "memory");
        } else {
            asm volatile("cp.async.wait_group 0;" ::: "memory");
        }
        __syncthreads();
        if (c + 2 < nchunk) {
            int nb = buf + 2; if (nb >= 3) nb -= 3;
            stage(c + 2, nb);
        }

        const __half* sA = (const __half*)sm_raw + buf * (G_BUF / 2);
        const __half* sB = sA + G_ARR / 2;

#pragma unroll
        for (int ks = 0; ks < 2; ks++) {
            unsigned ah[4][4], bw[2][4];
#pragma unroll
            for (int i = 0; i < 4; i++)
                ldsm_x4(ah[i], sA + (wm * 64 + i * 16 + a_r) * 40 + ks * 16 + a_c);
#pragma unroll
            for (int i = 0; i < 2; i++)
                ldsm_x4(bw[i], sB + (wn * 32 + i * 16 + b_r) * 40 + ks * 16 + b_c);
#pragma unroll
            for (int i = 0; i < 4; i++)
#pragma unroll
                for (int j = 0; j < 4; j++)
                    mma_f16(acc[i][j], ah[i], &bw[j >> 1][(j & 1) * 2]);
        }
        buf++; if (buf >= 3) buf -= 3;
    }

#pragma unroll
    for (int i = 0; i < 4; i++)
#pragma unroll
        for (int j = 0; j < 4; j++) {
            int r  = row0 + wm * 64 + i * 16 + (lane >> 2);
            int cc = col0 + wn * 32 + j * 8 + (lane & 3) * 2;
            float2 f0 = make_float2(acc[i][j][0] * scale, acc[i][j][1] * scale);
            float2 f1 = make_float2(acc[i][j][2] * scale, acc[i][j][3] * scale);
            if (OUT == 0) {
                *(float2*)&C[(size_t)r * N + cc]       = f0;
                *(float2*)&C[(size_t)(r + 8) * N + cc] = f1;
            } else {
                *(unsigned*)&Ch[(size_t)r * N + cc]       = pack_hf2(f0);
                *(unsigned*)&Ch[(size_t)(r + 8) * N + cc] = pack_hf2(f1);
            }
        }
}

// Fused Q/K/V projection: blockIdx.z selects weight/output/scale.
__global__ __launch_bounds__(256, 2) void gemm_qkv(
    const __half* __restrict__ x16,
    const __half* __restrict__ wq16, const __half* __restrict__ wk16,
    const __half* __restrict__ wv16,
    __half* __restrict__ Q16, __half* __restrict__ K16, __half* __restrict__ V16,
    float qscale)
{
    const int z = blockIdx.z;
    const __half* B = (z == 0) ? wq16 : (z == 1) ? wk16 : wv16;
    __half* Ch      = (z == 0) ? Q16  : (z == 1) ? K16  : V16;
    float scale     = (z == 0) ? qscale : 1.0f;
    gemm_body<1>(x16, B, nullptr, Ch, scale, blockIdx.y * 128, blockIdx.x * 128);
}

// O projection: fp32 output.
__global__ __launch_bounds__(256, 2) void gemm_o(
    const __half* __restrict__ Oa16, const __half* __restrict__ wo16,
    float* __restrict__ out)
{
    gemm_body<0>(Oa16, wo16, out, nullptr, 1.0f, blockIdx.y * 128, blockIdx.x * 128);
}

// ---------------------------------------------------------------------------
// Flash attention: causal, no online max, fp16 operands, fp32 accum.
// 128-key pipeline stages, computed as two 64-key halves with independent
// causal skip (same mma count as 64-key staging, half the barriers).
// Softmax via ex2.approx.f16x2. Block 256 thr (8 warps x 16 q-rows),
// double-buffered cp.async, 2 CTAs/SM. Output: single fp16.
// ---------------------------------------------------------------------------
#define SEGK  9216            // 128*72 halves per array (K or V)
#define A_BUF2 (2 * SEGK)     // K + V per buffer
extern __shared__ __align__(16) __half sm_att[];

__global__ __launch_bounds__(256, 2) void flash_attn_tc(
    const __half* __restrict__ Q16,
    const __half* __restrict__ K16,
    const __half* __restrict__ V16,
    __half* __restrict__ Oa16)
{
    const int tid  = threadIdx.x;
    const int lane = tid & 31;
    const int wid  = tid >> 5;
    const int qt   = gridDim.x - 1 - blockIdx.x;   // heavy blocks first
    const int q0   = qt * 128;
    const int h    = blockIdx.y;
    const int b    = blockIdx.z;
    const int bS   = b * S_LEN;
    const int hoff = h * DKH;

    // Stage Q tile (128x64 fp16) into buffer 0's K array, extract fragments.
    {
        int r = tid >> 1;
        int c0 = (tid & 1) * 32;
        size_t g = (size_t)(bS + q0 + r) * DM + hoff + c0;
        __half* d = sm_att + r * 72 + c0;
#pragma unroll
        for (int u = 0; u < 4; u++)
            *(uint4*)(d + u * 8) = *(const uint4*)(Q16 + g + u * 8);
    }
    __syncthreads();

    unsigned qa[4][4];
    {
        int rr = wid * 16 + (lane & 15);
        int cc = (lane >> 4) << 3;
#pragma unroll
        for (int kc = 0; kc < 4; kc++)
            ldsm_x4(qa[kc], sm_att + rr * 72 + kc * 16 + cc);
    }
    __syncthreads();

    float o[8][4];
#pragma unroll
    for (int j = 0; j < 8; j++)
#pragma unroll
        for (int e = 0; e < 4; e++) o[j][e] = 0.f;
    float lsum0 = 0.f, lsum1 = 0.f;

    const int wq = q0 + wid * 16;
    const int nst = qt + 1;              // 128-key stages

    auto stage = [&](int kt2, int bb) {
        size_t gbase = (size_t)(bS + kt2 * 128) * DM + hoff;
        __half* bK = sm_att + bb * A_BUF2;
        __half* bV = bK + SEGK;
#pragma unroll
        for (int u = 0; u < 4; u++) {
            int idx = tid * 4 + u;           // 0..1023
            int r = idx >> 3;
            int c = (idx & 7) * 8;
            size_t g = gbase + (size_t)r * DM + c;
            int so = r * 72 + c;
            cp16(bK + so, K16 + g);
            cp16(bV + so, V16 + g);
        }
        cp_commit();
    };

    stage(0, 0);
    int cur = 0;

    const int kb_r = ((lane >> 4) << 3) + (lane & 7);
    const int kb_c = ((lane >> 3) & 1) << 3;
    const int v_r  = lane & 15;
    const int v_c  = (lane >> 4) << 3;

    for (int kt2 = 0; kt2 < nst; kt2++) {
        cp_wait0();
        __syncthreads();
        if (kt2 + 1 < nst) stage(kt2 + 1, cur ^ 1);

        const __half* cK = sm_att + cur * A_BUF2;
        const __half* cV = cK + SEGK;

#pragma unroll
        for (int half = 0; half < 2; half++) {
            const int kb = kt2 * 128 + half * 64;
            if (kb > wq + 15) continue;     // fully masked for this warp

            const __half* bK = cK + half * 64 * 72;
            const __half* bV = cV + half * 64 * 72;

            float s[8][4];
#pragma unroll
            for (int j = 0; j < 8; j++)
#pragma unroll
                for (int e = 0; e < 4; e++) s[j][e] = 0.f;

            // ---- S = Q K^T (single fp16, fp32 accum)
#pragma unroll
            for (int kc = 0; kc < 4; kc++) {
                unsigned kf[4][4];
#pragma unroll
                for (int g = 0; g < 4; g++)
                    ldsm_x4(kf[g], bK + (g * 16 + kb_r) * 72 + kc * 16 + kb_c);
#pragma unroll
                for (int g = 0; g < 4; g++)
#pragma unroll
                    for (int sub = 0; sub < 2; sub++)
                        mma_f16(s[g * 2 + sub], qa[kc], &kf[g][sub * 2]);
            }

            // ---- p = exp2(s) via ex2.approx.f16x2 (result = packed P frag)
            const int qrel = wq + (lane >> 2) - kb;
#pragma unroll
            for (int j = 0; j < 8; j++) {
                int kc0 = j * 8 + ((lane & 3) << 1);
                float s0 = (kc0     <= qrel)     ? s[j][0] : -3.0e4f;
                float s1 = (kc0 + 1 <= qrel)     ? s[j][1] : -3.0e4f;
                float s2 = (kc0     <= qrel + 8) ? s[j][2] : -3.0e4f;
                float s3 = (kc0 + 1 <= qrel + 8) ? s[j][3] : -3.0e4f;
                unsigned h01, h23, p01, p23;
                asm("cvt.rn.f16x2.f32 %0, %1, %2;" : "=r"(h01) : "f"(s1), "f"(s0));
                asm("cvt.rn.f16x2.f32 %0, %1, %2;" : "=r"(h23) : "f"(s3), "f"(s2));
                asm("ex2.approx.f16x2 %0, %1;" : "=r"(p01) : "r"(h01));
                asm("ex2.approx.f16x2 %0, %1;" : "=r"(p23) : "r"(h23));
                s[j][0] = __uint_as_float(p01);
                s[j][1] = __uint_as_float(p23);
                float2 f0 = __half22float2(*(__half2*)&p01);
                float2 f1 = __half22float2(*(__half2*)&p23);
                lsum0 += f0.x + f0.y;
                lsum1 += f1.x + f1.y;
            }

            // ---- O += P V (single fp16 P and V)
#pragma unroll
            for (int kc = 0; kc < 4; kc++) {
                unsigned pa[4];
                pa[0] = __float_as_uint(s[2 * kc][0]);
                pa[1] = __float_as_uint(s[2 * kc][1]);
                pa[2] = __float_as_uint(s[2 * kc + 1][0]);
                pa[3] = __float_as_uint(s[2 * kc + 1][1]);
                unsigned vb[4][4];
#pragma unroll
                for (int g = 0; g < 4; g++)
                    ldsm_x4_t(vb[g], bV + (kc * 16 + v_r) * 72 + g * 16 + v_c);
#pragma unroll
                for (int g = 0; g < 4; g++)
#pragma unroll
                    for (int sub = 0; sub < 2; sub++)
                        mma_f16(o[g * 2 + sub], pa, &vb[g][sub * 2]);
            }
        }
        cur ^= 1;
    }

    lsum0 += __shfl_xor_sync(0xffffffffu, lsum0, 1);
    lsum0 += __shfl_xor_sync(0xffffffffu, lsum0, 2);
    lsum1 += __shfl_xor_sync(0xffffffffu, lsum1, 1);
    lsum1 += __shfl_xor_sync(0xffffffffu, lsum1, 2);
    const float inv0 = 1.f / lsum0;
    const float inv1 = 1.f / lsum1;

    const int row0 = bS + q0 + wid * 16 + (lane >> 2);
#pragma unroll
    for (int j = 0; j < 8; j++) {
        int cc = hoff + j * 8 + (lane & 3) * 2;
        float2 f0 = make_float2(o[j][0] * inv0, o[j][1] * inv0);
        float2 f1 = make_float2(o[j][2] * inv1, o[j][3] * inv1);
        *(unsigned*)&Oa16[(size_t)row0 * DM + cc]       = pack_hf2(f0);
        *(unsigned*)&Oa16[(size_t)(row0 + 8) * DM + cc] = pack_hf2(f1);
    }
}

// ---------------------------------------------------------------------------
extern "C" void kernel_launch(void* const* d_in, const int* in_sizes, int n_in,
                              void* d_out, int out_size)
{
    const float* x  = (const float*)d_in[0];
    const float* wq = (const float*)d_in[1];
    const float* wk = (const float*)d_in[2];
    const float* wv = (const float*)d_in[3];
    const float* wo = (const float*)d_in[4];
    float* out = (float*)d_out;

    __half *x16, *wq16, *wk16, *wv16, *wo16;
    __half *Q16, *K16, *V16, *Oa16;
    cudaGetSymbolAddress((void**)&x16, g_x16);
    cudaGetSymbolAddress((void**)&wq16, g_wq16); cudaGetSymbolAddress((void**)&wk16, g_wk16);
    cudaGetSymbolAddress((void**)&wv16, g_wv16); cudaGetSymbolAddress((void**)&wo16, g_wo16);
    cudaGetSymbolAddress((void**)&Q16, g_Q16);   cudaGetSymbolAddress((void**)&K16, g_K16);
    cudaGetSymbolAddress((void**)&V16, g_V16);   cudaGetSymbolAddress((void**)&Oa16, g_Oa16);

    round_all<<<RSTRIDE / 256, 256>>>(x, wq, wk, wv, wo, x16, wq16, wk16, wv16, wo16);

    cudaFuncSetAttribute(gemm_qkv, cudaFuncAttributeMaxDynamicSharedMemorySize, G_SMEM);
    cudaFuncSetAttribute(gemm_o,   cudaFuncAttributeMaxDynamicSharedMemorySize, G_SMEM);

    const float qscale = 0.125f * 1.4426950408889634f;
    dim3 gq(DM / 128, MROWS / 128, 3);   // (8, 32, 3)
    gemm_qkv<<<gq, 256, G_SMEM>>>(x16, wq16, wk16, wv16, Q16, K16, V16, qscale);

    const int smbytes = 2 * A_BUF2 * (int)sizeof(__half);   // 73728
    cudaFuncSetAttribute(flash_attn_tc, cudaFuncAttributeMaxDynamicSharedMemorySize, smbytes);
    dim3 attnGrid(S_LEN / 128, NH, BATCH);  // (16, 16, 2)
    flash_attn_tc<<<attnGrid, 256, smbytes>>>(Q16, K16, V16, Oa16);

    dim3 go(DM / 128, MROWS / 128);      // (8, 32)
    gemm_o<<<go, 256, G_SMEM>>>(Oa16, wo16, out);
}

// round 16
// speedup vs baseline: 1.0404x; 1.0404x over previous
#include <cuda_runtime.h>
#include <cuda_bf16.h>
#include <cuda_fp16.h>
#include <cstdint>

// Problem constants
#define S_LEN 2048
#define BATCH 2
#define DM    1024
#define NH    16
#define DKH   64
#define MROWS (BATCH * S_LEN)   // 4096

// ---------------------------------------------------------------------------
// Scratch (__device__ globals)
// ---------------------------------------------------------------------------
__device__ __half g_x16[(size_t)MROWS * DM];
__device__ __half g_wq16[(size_t)DM * DM];
__device__ __half g_wk16[(size_t)DM * DM];
__device__ __half g_wv16[(size_t)DM * DM];
__device__ __half g_wo16[(size_t)DM * DM];

__device__ __half g_Q16[(size_t)MROWS * DM];
__device__ __half g_K16[(size_t)MROWS * DM];
__device__ __half g_V16[(size_t)MROWS * DM];
__device__ __half g_Oa16[(size_t)MROWS * DM];

// ---------------------------------------------------------------------------
// Fused fp32 -> fp16 round of x + 4 weights, MLP=4 per thread
// ---------------------------------------------------------------------------
#define NX4 (MROWS * DM / 4)     // 1048576
#define NW4 (DM * DM / 4)        // 262144 = 1<<18
#define NTOT (NX4 + 4 * NW4)     // 2097152
#define RSTRIDE (NTOT / 4)       // 524288

__global__ __launch_bounds__(256) void round_all(
    const float* __restrict__ x,
    const float* __restrict__ wq, const float* __restrict__ wk,
    const float* __restrict__ wv, const float* __restrict__ wo,
    __half* __restrict__ x16,
    __half* __restrict__ wq16, __half* __restrict__ wk16,
    __half* __restrict__ wv16, __half* __restrict__ wo16)
{
    const int base = blockIdx.x * 256 + threadIdx.x;
    float4 v[4];
    __half2* dsts[4];
#pragma unroll
    for (int u = 0; u < 4; u++) {
        int i = base + u * RSTRIDE;
        const float* src;
        __half* dst;
        int off;
        if (i < NX4) {
            src = x; dst = x16; off = i;
        } else {
            int j = i - NX4;
            int w = j >> 18;
            off = j & (NW4 - 1);
            src = (w == 0) ? wq : (w == 1) ? wk : (w == 2) ? wv : wo;
            dst = (w == 0) ? wq16 : (w == 1) ? wk16 : (w == 2) ? wv16 : wo16;
        }
        v[u] = ((const float4*)src)[off];
        dsts[u] = ((__half2*)dst) + 2 * off;
    }
#pragma unroll
    for (int u = 0; u < 4; u++) {
        dsts[u][0] = __float22half2_rn(make_float2(v[u].x, v[u].y));
        dsts[u][1] = __float22half2_rn(make_float2(v[u].z, v[u].w));
    }
}

// ---------------------------------------------------------------------------
// Common helpers
// ---------------------------------------------------------------------------
__device__ __forceinline__ void ldsm_x4(unsigned* r, const void* p) {
    unsigned addr = (unsigned)__cvta_generic_to_shared(p);
    asm volatile("ldmatrix.sync.aligned.m8n8.x4.shared.b16 {%0,%1,%2,%3},[%4];"
                 : "=r"(r[0]), "=r"(r[1]), "=r"(r[2]), "=r"(r[3]) : "r"(addr));
}
__device__ __forceinline__ void ldsm_x4_t(unsigned* r, const void* p) {
    unsigned addr = (unsigned)__cvta_generic_to_shared(p);
    asm volatile("ldmatrix.sync.aligned.m8n8.x4.trans.shared.b16 {%0,%1,%2,%3},[%4];"
                 : "=r"(r[0]), "=r"(r[1]), "=r"(r[2]), "=r"(r[3]) : "r"(addr));
}
__device__ __forceinline__ void mma_f16(float* d, const unsigned* a, const unsigned* b) {
    asm volatile(
        "mma.sync.aligned.m16n8k16.row.col.f32.f16.f16.f32 "
        "{%0,%1,%2,%3},{%4,%5,%6,%7},{%8,%9},{%0,%1,%2,%3};"
        : "+f"(d[0]), "+f"(d[1]), "+f"(d[2]), "+f"(d[3])
        : "r"(a[0]), "r"(a[1]), "r"(a[2]), "r"(a[3]), "r"(b[0]), "r"(b[1]));
}
__device__ __forceinline__ void cp16(void* smem, const void* g) {
    unsigned s = (unsigned)__cvta_generic_to_shared(smem);
    asm volatile("cp.async.cg.shared.global [%0], [%1], 16;" :: "r"(s), "l"(g));
}
__device__ __forceinline__ void cp16s(unsigned s, const void* g) {
    asm volatile("cp.async.cg.shared.global [%0], [%1], 16;" :: "r"(s), "l"(g));
}
__device__ __forceinline__ void cp_commit() { asm volatile("cp.async.commit_group;"); }
__device__ __forceinline__ void cp_wait0()  { asm volatile("cp.async.wait_group 0;"); }
__device__ __forceinline__ unsigned pack_hf2(float2 f) {
    __half2 h = __float22half2_rn(f);
    return *(unsigned*)&h;
}

// ---------------------------------------------------------------------------
// Shared GEMM config: block 128x128, 256 thr (8 warps, 2x4), warp tile 64x32,
// K-chunk 32, 3-stage cp.async pipeline, 2 CTAs/SM.
// ---------------------------------------------------------------------------
#define G_ARR   10240                  // bytes per smem array (128 x 40 halves)
#define G_BUF   (2 * G_ARR)            // A, B = 20480
#define G_SMEM  (3 * G_BUF)            // 61440 (3 stages)

extern __shared__ char sm_raw[];

// fp32-accumulator GEMM body (OUT: 0 = fp32 out, 1 = fp16 out)
template<int OUT>
__device__ __forceinline__ void gemm_body(
    const __half* __restrict__ A, const __half* __restrict__ B,
    float* __restrict__ C, __half* __restrict__ Ch,
    float scale, int row0, int col0)
{
    const int tid  = threadIdx.x;
    const int lane = tid & 31;
    const int wid  = tid >> 5;
    const int wm   = wid & 1;
    const int wn   = wid >> 1;
    const int N = DM, K = DM;

    const unsigned smem_u = (unsigned)__cvta_generic_to_shared(sm_raw);

    float acc[4][4][4];
#pragma unroll
    for (int i = 0; i < 4; i++)
#pragma unroll
        for (int j = 0; j < 4; j++)
#pragma unroll
            for (int e = 0; e < 4; e++) acc[i][j][e] = 0.f;

    const int a_r = lane & 15;
    const int a_c = (lane >> 4) << 3;
    const int b_r = ((lane >> 4) << 3) + (lane & 7);
    const int b_c = ((lane >> 3) & 1) << 3;

    auto stage = [&](int c, int bb) {
        const int kk = c * 32;
        const unsigned base = smem_u + bb * G_BUF;
#pragma unroll
        for (int u = 0; u < 2; u++) {
            int g = tid + u * 256;
            int r = g >> 2;
            int q = (g & 3) * 8;
            size_t ga = (size_t)(row0 + r) * K + kk + q;
            size_t gb = (size_t)(col0 + r) * K + kk + q;
            unsigned so = (unsigned)(r * 40 + q) * 2;
            cp16s(base + so,         A + ga);
            cp16s(base + G_ARR + so, B + gb);
        }
        cp_commit();
    };

    const int nchunk = K / 32;           // 32
    stage(0, 0);
    stage(1, 1);

    int buf = 0;
    for (int c = 0; c < nchunk; c++) {
        if (c + 1 < nchunk) {
            asm volatile("cp.async.wait_group 1;" ::: "memory");
        } else {
            asm volatile("cp.async.wait_group 0;" ::: "memory");
        }
        __syncthreads();
        if (c + 2 < nchunk) {
            int nb = buf + 2; if (nb >= 3) nb -= 3;
            stage(c + 2, nb);
        }

        const __half* sA = (const __half*)sm_raw + buf * (G_BUF / 2);
        const __half* sB = sA + G_ARR / 2;

#pragma unroll
        for (int ks = 0; ks < 2; ks++) {
            unsigned ah[4][4], bw[2][4];
#pragma unroll
            for (int i = 0; i < 4; i++)
                ldsm_x4(ah[i], sA + (wm * 64 + i * 16 + a_r) * 40 + ks * 16 + a_c);
#pragma unroll
            for (int i = 0; i < 2; i++)
                ldsm_x4(bw[i], sB + (wn * 32 + i * 16 + b_r) * 40 + ks * 16 + b_c);
#pragma unroll
            for (int i = 0; i < 4; i++)
#pragma unroll
                for (int j = 0; j < 4; j++)
                    mma_f16(acc[i][j], ah[i], &bw[j >> 1][(j & 1) * 2]);
        }
        buf++; if (buf >= 3) buf -= 3;
    }

#pragma unroll
    for (int i = 0; i < 4; i++)
#pragma unroll
        for (int j = 0; j < 4; j++) {
            int r  = row0 + wm * 64 + i * 16 + (lane >> 2);
            int cc = col0 + wn * 32 + j * 8 + (lane & 3) * 2;
            float2 f0 = make_float2(acc[i][j][0] * scale, acc[i][j][1] * scale);
            float2 f1 = make_float2(acc[i][j][2] * scale, acc[i][j][3] * scale);
            if (OUT == 0) {
                *(float2*)&C[(size_t)r * N + cc]       = f0;
                *(float2*)&C[(size_t)(r + 8) * N + cc] = f1;
            } else {
                *(unsigned*)&Ch[(size_t)r * N + cc]       = pack_hf2(f0);
                *(unsigned*)&Ch[(size_t)(r + 8) * N + cc] = pack_hf2(f1);
            }
        }
}

// Fused Q/K/V projection: blockIdx.z selects weight/output/scale.
__global__ __launch_bounds__(256, 2) void gemm_qkv(
    const __half* __restrict__ x16,
    const __half* __restrict__ wq16, const __half* __restrict__ wk16,
    const __half* __restrict__ wv16,
    __half* __restrict__ Q16, __half* __restrict__ K16, __half* __restrict__ V16,
    float qscale)
{
    const int z = blockIdx.z;
    const __half* B = (z == 0) ? wq16 : (z == 1) ? wk16 : wv16;
    __half* Ch      = (z == 0) ? Q16  : (z == 1) ? K16  : V16;
    float scale     = (z == 0) ? qscale : 1.0f;
    gemm_body<1>(x16, B, nullptr, Ch, scale, blockIdx.y * 128, blockIdx.x * 128);
}

// O projection: fp32 output.
__global__ __launch_bounds__(256, 2) void gemm_o(
    const __half* __restrict__ Oa16, const __half* __restrict__ wo16,
    float* __restrict__ out)
{
    gemm_body<0>(Oa16, wo16, out, nullptr, 1.0f, blockIdx.y * 128, blockIdx.x * 128);
}

// ---------------------------------------------------------------------------
// Flash attention (R14 config): causal, no online max, fp16 operands, fp32
// accum. S = Q K^T (1 mma). Softmax via ex2.approx.f16x2. O += P V (1 mma).
// Block 256 thr (8 warps x 16 q-rows), key tile 64, double-buffered cp.async,
// 2 CTAs/SM. Output: single fp16.
// ---------------------------------------------------------------------------
#define SEG 4608          // 64*72 halves per array
#define A_BUF (2 * SEG)   // K, V
extern __shared__ __align__(16) __half sm_att[];

__global__ __launch_bounds__(256, 2) void flash_attn_tc(
    const __half* __restrict__ Q16,
    const __half* __restrict__ K16,
    const __half* __restrict__ V16,
    __half* __restrict__ Oa16)
{
    const int tid  = threadIdx.x;
    const int lane = tid & 31;
    const int wid  = tid >> 5;
    const int q0   = (gridDim.x - 1 - blockIdx.x) * 128;   // heavy blocks first
    const int h    = blockIdx.y;
    const int b    = blockIdx.z;
    const int bS   = b * S_LEN;
    const int hoff = h * DKH;

    __half* bufp[2][2];
#pragma unroll
    for (int bb = 0; bb < 2; bb++)
#pragma unroll
        for (int a = 0; a < 2; a++) bufp[bb][a] = sm_att + bb * A_BUF + a * SEG;

    // Stage Q tile (128x64 fp16) into buf0 (rows 0-63 -> arr0, 64-127 -> arr1)
    {
        int r = tid >> 1;
        int c0 = (tid & 1) * 32;
        size_t g = (size_t)(bS + q0 + r) * DM + hoff + c0;
        __half* d = (r < 64) ? bufp[0][0] + r * 72 + c0 : bufp[0][1] + (r - 64) * 72 + c0;
#pragma unroll
        for (int u = 0; u < 4; u++)
            *(uint4*)(d + u * 8) = *(const uint4*)(Q16 + g + u * 8);
    }
    __syncthreads();

    unsigned qa[4][4];
    {
        const __half* sq = (wid < 4) ? bufp[0][0] : bufp[0][1];
        int rr = (wid & 3) * 16 + (lane & 15);
        int cc = (lane >> 4) << 3;
#pragma unroll
        for (int kc = 0; kc < 4; kc++)
            ldsm_x4(qa[kc], sq + rr * 72 + kc * 16 + cc);
    }
    __syncthreads();

    float o[8][4];
#pragma unroll
    for (int j = 0; j < 8; j++)
#pragma unroll
        for (int e = 0; e < 4; e++) o[j][e] = 0.f;
    float lsum0 = 0.f, lsum1 = 0.f;

    const int ntiles = q0 / 64 + 2;
    const int wq = q0 + wid * 16;

    auto stage = [&](int kt, int bb) {
        size_t gbase = (size_t)(bS + kt * 64) * DM + hoff;
#pragma unroll
        for (int u = 0; u < 2; u++) {
            int idx = tid * 2 + u;
            int r = idx >> 3;
            int c = (idx & 7) * 8;
            size_t g = gbase + (size_t)r * DM + c;
            int so = r * 72 + c;
            cp16(bufp[bb][0] + so, K16 + g);
            cp16(bufp[bb][1] + so, V16 + g);
        }
        cp_commit();
    };

    stage(0, 0);
    int cur = 0;

    const int kb_r = ((lane >> 4) << 3) + (lane & 7);
    const int kb_c = ((lane >> 3) & 1) << 3;
    const int v_r  = lane & 15;
    const int v_c  = (lane >> 4) << 3;

    for (int kt = 0; kt < ntiles; kt++) {
        cp_wait0();
        __syncthreads();
        if (kt + 1 < ntiles) stage(kt + 1, cur ^ 1);

        if (kt * 64 <= wq + 15) {
            const __half* bK = bufp[cur][0];
            const __half* bV = bufp[cur][1];

            float s[8][4];
#pragma unroll
            for (int j = 0; j < 8; j++)
#pragma unroll
                for (int e = 0; e < 4; e++) s[j][e] = 0.f;

            // ---- S = Q K^T (single fp16, fp32 accum)
#pragma unroll
            for (int kc = 0; kc < 4; kc++) {
                unsigned kb[4][4];
#pragma unroll
                for (int g = 0; g < 4; g++)
                    ldsm_x4(kb[g], bK + (g * 16 + kb_r) * 72 + kc * 16 + kb_c);
#pragma unroll
                for (int g = 0; g < 4; g++)
#pragma unroll
                    for (int sub = 0; sub < 2; sub++)
                        mma_f16(s[g * 2 + sub], qa[kc], &kb[g][sub * 2]);
            }

            // ---- p = exp2(s) via ex2.approx.f16x2 (result = packed P frag)
            const int qrel = wq + (lane >> 2) - kt * 64;
#pragma unroll
            for (int j = 0; j < 8; j++) {
                int kc0 = j * 8 + ((lane & 3) << 1);
                float s0 = (kc0     <= qrel)     ? s[j][0] : -3.0e4f;
                float s1 = (kc0 + 1 <= qrel)     ? s[j][1] : -3.0e4f;
                float s2 = (kc0     <= qrel + 8) ? s[j][2] : -3.0e4f;
                float s3 = (kc0 + 1 <= qrel + 8) ? s[j][3] : -3.0e4f;
                unsigned h01, h23, p01, p23;
                asm("cvt.rn.f16x2.f32 %0, %1, %2;" : "=r"(h01) : "f"(s1), "f"(s0));
                asm("cvt.rn.f16x2.f32 %0, %1, %2;" : "=r"(h23) : "f"(s3), "f"(s2));
                asm("ex2.approx.f16x2 %0, %1;" : "=r"(p01) : "r"(h01));
                asm("ex2.approx.f16x2 %0, %1;" : "=r"(p23) : "r"(h23));
                s[j][0] = __uint_as_float(p01);
                s[j][1] = __uint_as_float(p23);
                float2 f0 = __half22float2(*(__half2*)&p01);
                float2 f1 = __half22float2(*(__half2*)&p23);
                lsum0 += f0.x + f0.y;
                lsum1 += f1.x + f1.y;
            }

            // ---- O += P V (single fp16 P and V)
#pragma unroll
            for (int kc = 0; kc < 4; kc++) {
                unsigned pa[4];
                pa[0] = __float_as_uint(s[2 * kc][0]);
                pa[1] = __float_as_uint(s[2 * kc][1]);
                pa[2] = __float_as_uint(s[2 * kc + 1][0]);
                pa[3] = __float_as_uint(s[2 * kc + 1][1]);
                unsigned vb[4][4];
#pragma unroll
                for (int g = 0; g < 4; g++)
                    ldsm_x4_t(vb[g], bV + (kc * 16 + v_r) * 72 + g * 16 + v_c);
#pragma unroll
                for (int g = 0; g < 4; g++)
#pragma unroll
                    for (int sub = 0; sub < 2; sub++)
                        mma_f16(o[g * 2 + sub], pa, &vb[g][sub * 2]);
            }
        }
        cur ^= 1;
    }

    lsum0 += __shfl_xor_sync(0xffffffffu, lsum0, 1);
    lsum0 += __shfl_xor_sync(0xffffffffu, lsum0, 2);
    lsum1 += __shfl_xor_sync(0xffffffffu, lsum1, 1);
    lsum1 += __shfl_xor_sync(0xffffffffu, lsum1, 2);
    const float inv0 = 1.f / lsum0;
    const float inv1 = 1.f / lsum1;

    const int row0 = bS + q0 + wid * 16 + (lane >> 2);
#pragma unroll
    for (int j = 0; j < 8; j++) {
        int cc = hoff + j * 8 + (lane & 3) * 2;
        float2 f0 = make_float2(o[j][0] * inv0, o[j][1] * inv0);
        float2 f1 = make_float2(o[j][2] * inv1, o[j][3] * inv1);
        *(unsigned*)&Oa16[(size_t)row0 * DM + cc]       = pack_hf2(f0);
        *(unsigned*)&Oa16[(size_t)(row0 + 8) * DM + cc] = pack_hf2(f1);
    }
}

// ---------------------------------------------------------------------------
extern "C" void kernel_launch(void* const* d_in, const int* in_sizes, int n_in,
                              void* d_out, int out_size)
{
    const float* x  = (const float*)d_in[0];
    const float* wq = (const float*)d_in[1];
    const float* wk = (const float*)d_in[2];
    const float* wv = (const float*)d_in[3];
    const float* wo = (const float*)d_in[4];
    float* out = (float*)d_out;

    __half *x16, *wq16, *wk16, *wv16, *wo16;
    __half *Q16, *K16, *V16, *Oa16;
    cudaGetSymbolAddress((void**)&x16, g_x16);
    cudaGetSymbolAddress((void**)&wq16, g_wq16); cudaGetSymbolAddress((void**)&wk16, g_wk16);
    cudaGetSymbolAddress((void**)&wv16, g_wv16); cudaGetSymbolAddress((void**)&wo16, g_wo16);
    cudaGetSymbolAddress((void**)&Q16, g_Q16);   cudaGetSymbolAddress((void**)&K16, g_K16);
    cudaGetSymbolAddress((void**)&V16, g_V16);   cudaGetSymbolAddress((void**)&Oa16, g_Oa16);

    round_all<<<RSTRIDE / 256, 256>>>(x, wq, wk, wv, wo, x16, wq16, wk16, wv16, wo16);

    cudaFuncSetAttribute(gemm_qkv, cudaFuncAttributeMaxDynamicSharedMemorySize, G_SMEM);
    cudaFuncSetAttribute(gemm_o,   cudaFuncAttributeMaxDynamicSharedMemorySize, G_SMEM);

    const float qscale = 0.125f * 1.4426950408889634f;
    dim3 gq(DM / 128, MROWS / 128, 3);   // (8, 32, 3)
    gemm_qkv<<<gq, 256, G_SMEM>>>(x16, wq16, wk16, wv16, Q16, K16, V16, qscale);

    const int smbytes = 2 * A_BUF * (int)sizeof(__half);   // 36864
    cudaFuncSetAttribute(flash_attn_tc, cudaFuncAttributeMaxDynamicSharedMemorySize, smbytes);
    dim3 attnGrid(S_LEN / 128, NH, BATCH);  // (16, 16, 2)
    flash_attn_tc<<<attnGrid, 256, smbytes>>>(Q16, K16, V16, Oa16);

    dim3 go(DM / 128, MROWS / 128);      // (8, 32)
    gemm_o<<<go, 256, G_SMEM>>>(Oa16, wo16, out);
}